// round 4
// baseline (speedup 1.0000x reference)
#include <cuda_runtime.h>

// CapsuleConvTranspose2d (2,64,32,32) -> (2,64,64,64): stride-2 3x3 transposed
// conv into 8 out-capsules x 8 dims, 3-iter k-means routing, squash, bias.
//
// patch[n,c,kh,kw,p,q] = x[n,c,(p+kh-1)/2,(q+kw-1)/2] iff (p+kh-1) even and the
// index is in range, else 0. Valid kh depends only on parity of p (even->{1},
// odd->{0,2}); same for q/kw. Border (p or q = 63, tap=2) is zero-filled: a
// zero prior routes identically to a structurally-absent one (exp(-lmax) in Z).
//
// Block = 128 threads, one (n,p) row segment of 16 q values.
//   group 0 (threads 0-63):  8 even-q pixels     group 1: 8 odd-q pixels
// Per block, staged once: weights (<=6 taps, [slab][l][g][m]) and the x working
// set (<=2 rows x 64ch x 9 j) in transposed layout [a][l*8+f][j'] (pitch 9, odd
// -> conflict-free lane reads). Pixel loop is barrier-free: priors live in
// registers, routing is register+shuffle (width 8). Output via padded smem then
// one coalesced writeback.

#define WP 520            // weight slab pitch (floats), 16B aligned
#define XP 576            // x slot pitch = 64*9
#define OP 17             // s_out row pitch (odd -> no conflicts)

template<int NKH, int NKW>
__device__ __forceinline__ void caps_group(
    int n, int p, int qbase, int j0,
    const float* __restrict__ s_w, const float* __restrict__ s_x2,
    float* __restrict__ s_out, const float* __restrict__ bs, int qs16)
{
    constexpr int NTAP  = NKH * NKW;          // priors per lane
    constexpr int CNT   = NTAP;
    constexpr int FSTEP = 8 / NTAP;
    constexpr float NZEROS = (float)(72 - 8 * NTAP);
    const unsigned FULL = 0xffffffffu;

    const int t64 = threadIdx.x & 63;
    const int g = t64 >> 3;
    const int r = t64 & 7;

    const int tp = r & (NTAP - 1);
    const int a  = tp / NKW;                  // kh slot
    const int b  = tp % NKW;                  // kw slot
    const int kw = (NKW == 1) ? 1 : (b << 1);
    const int f0 = r / NTAP;

    const float* wrow  = s_w  + (a * 3 + kw) * WP + g * 8;
    const float* xbase = s_x2 + a * XP + f0 * 9;
    const float  bsv   = __ldg(&bs[t64]);

    #pragma unroll
    for (int jdx = 0; jdx < 8; jdx++) {
        const int q  = qbase + 2 * jdx;
        const int jj = ((q + kw - 1) >> 1) - j0;
        const float* xptr = xbase + jj;

        // ---- priors in registers ----
        float pri[CNT][8];
        #pragma unroll
        for (int k = 0; k < CNT; k++)
            #pragma unroll
            for (int m = 0; m < 8; m++) pri[k][m] = 0.f;

        #pragma unroll
        for (int l = 0; l < 8; l++) {
            float4 w0 = *(const float4*)(wrow + l * 64);
            float4 w1 = *(const float4*)(wrow + l * 64 + 4);
            #pragma unroll
            for (int k = 0; k < CNT; k++) {
                float xv = xptr[l * 72 + k * (FSTEP * 9)];
                pri[k][0] = fmaf(xv, w0.x, pri[k][0]);
                pri[k][1] = fmaf(xv, w0.y, pri[k][1]);
                pri[k][2] = fmaf(xv, w0.z, pri[k][2]);
                pri[k][3] = fmaf(xv, w0.w, pri[k][3]);
                pri[k][4] = fmaf(xv, w1.x, pri[k][4]);
                pri[k][5] = fmaf(xv, w1.y, pri[k][5]);
                pri[k][6] = fmaf(xv, w1.z, pri[k][6]);
                pri[k][7] = fmaf(xv, w1.w, pri[k][7]);
            }
        }

        // ---- routing init: mean over all 72 (zeros included) ----
        float o[8];
        #pragma unroll
        for (int m = 0; m < 8; m++) {
            float s = pri[0][m];
            #pragma unroll
            for (int k = 1; k < CNT; k++) s += pri[k][m];
            o[m] = s;
        }
        #pragma unroll
        for (int d = 1; d < 8; d <<= 1)
            #pragma unroll
            for (int m = 0; m < 8; m++)
                o[m] += __shfl_xor_sync(FULL, o[m], d, 8);
        #pragma unroll
        for (int m = 0; m < 8; m++) o[m] *= (1.0f / 72.0f);

        #pragma unroll
        for (int it = 0; it < 3; it++) {
            float sn = 0.f;
            #pragma unroll
            for (int m = 0; m < 8; m++) sn = fmaf(o[m], o[m], sn);
            float inv = 1.0f / fmaxf(sqrtf(sn), 1e-12f);

            float lg[CNT];
            float lmax = 0.0f;                 // zero priors pin lmax >= 0
            #pragma unroll
            for (int k = 0; k < CNT; k++) {
                float s = 0.f;
                #pragma unroll
                for (int m = 0; m < 8; m++) s = fmaf(pri[k][m], o[m], s);
                s *= inv;
                lg[k] = s;
                lmax = fmaxf(lmax, s);
            }
            lmax = fmaxf(lmax, __shfl_xor_sync(FULL, lmax, 1, 8));
            lmax = fmaxf(lmax, __shfl_xor_sync(FULL, lmax, 2, 8));
            lmax = fmaxf(lmax, __shfl_xor_sync(FULL, lmax, 4, 8));

            float e[CNT];
            float z = 0.f;
            #pragma unroll
            for (int k = 0; k < CNT; k++) {
                e[k] = __expf(lg[k] - lmax);
                z += e[k];
            }
            z += __shfl_xor_sync(FULL, z, 1, 8);
            z += __shfl_xor_sync(FULL, z, 2, 8);
            z += __shfl_xor_sync(FULL, z, 4, 8);
            z += NZEROS * __expf(-lmax);

            float acc[8];
            #pragma unroll
            for (int m = 0; m < 8; m++) acc[m] = e[0] * pri[0][m];
            #pragma unroll
            for (int k = 1; k < CNT; k++)
                #pragma unroll
                for (int m = 0; m < 8; m++)
                    acc[m] = fmaf(e[k], pri[k][m], acc[m]);
            #pragma unroll
            for (int d = 1; d < 8; d <<= 1)
                #pragma unroll
                for (int m = 0; m < 8; m++)
                    acc[m] += __shfl_xor_sync(FULL, acc[m], d, 8);

            float rz = 1.0f / z;
            #pragma unroll
            for (int m = 0; m < 8; m++) o[m] = acc[m] * rz;
        }

        // ---- squash + bias ----
        float sn = 0.f;
        #pragma unroll
        for (int m = 0; m < 8; m++) sn = fmaf(o[m], o[m], sn);
        float scale = sn / ((1.0f + sn) * sqrtf(sn + 1e-12f));
        s_out[t64 * OP + (q - qs16)] = o[r] * scale + bsv;
    }
}

__global__ __launch_bounds__(128)
void caps_kernel(const float* __restrict__ x,
                 const float* __restrict__ wt,
                 const float* __restrict__ bs,
                 float* __restrict__ y)
{
    __shared__ float s_w[6 * WP];
    __shared__ float s_x2[2 * XP];
    __shared__ float s_out[64 * OP];

    const int bid  = blockIdx.x;
    const int qseg = bid & 3;
    const int p    = (bid >> 2) & 63;
    const int n    = bid >> 8;
    const int tid  = threadIdx.x;
    const int qs16 = qseg << 4;
    const int j0   = qseg << 3;

    const int podd = p & 1;
    const int nkh  = podd ? 2 : 1;

    // ---- stage weights: slab = a*3 + kw, layout [slab][l*64 + g*8 + m] ----
    {
        const int total = nkh * 3 * 512;
        for (int idx = tid; idx < total; idx += 128) {
            int slab = idx >> 9;
            int e    = idx & 511;
            int a    = (slab >= 3) ? 1 : 0;
            int kw   = slab - a * 3;
            int kh   = podd ? (a ? 2 : 0) : 1;
            int woff = (2 - kh) * 3 + (2 - kw);
            s_w[slab * WP + e] = wt[e * 9 + woff];
        }
    }

    // ---- stage x working set: [a][(c&7)*8 + c>>3][j'], coalesced loads ----
    {
        const int total = nkh * XP;
        for (int idx = tid; idx < total; idx += 128) {
            int a   = idx / XP;
            int rem = idx - a * XP;
            int c   = rem / 9;
            int jj  = rem - c * 9;
            int i   = podd ? ((p - 1 + 2 * a) >> 1) : (p >> 1);
            int j   = j0 + jj;
            float v = (i < 32 && j < 32) ? x[((n * 64 + c) * 32 + i) * 32 + j] : 0.f;
            int perm = ((c & 7) << 3) | (c >> 3);
            s_x2[a * XP + perm * 9 + jj] = v;
        }
    }
    __syncthreads();

    const int gid = tid >> 6;      // 0: even q, 1: odd q
    if (!podd) {
        if (gid == 0) caps_group<1, 1>(n, p, qs16,     j0, s_w, s_x2, s_out, bs, qs16);
        else          caps_group<1, 2>(n, p, qs16 + 1, j0, s_w, s_x2, s_out, bs, qs16);
    } else {
        if (gid == 0) caps_group<2, 1>(n, p, qs16,     j0, s_w, s_x2, s_out, bs, qs16);
        else          caps_group<2, 2>(n, p, qs16 + 1, j0, s_w, s_x2, s_out, bs, qs16);
    }
    __syncthreads();

    // ---- coalesced writeback: 64 channels x 16 q ----
    #pragma unroll
    for (int u = 0; u < 8; u++) {
        int idx = u * 128 + tid;
        int c   = idx >> 4;
        int col = idx & 15;
        y[((n * 64 + c) * 64 + p) * 64 + qs16 + col] = s_out[c * OP + col];
    }
}

extern "C" void kernel_launch(void* const* d_in, const int* in_sizes, int n_in,
                              void* d_out, int out_size) {
    const float* x  = (const float*)d_in[0];
    const float* wt = (const float*)d_in[1];
    const float* bs = (const float*)d_in[2];
    float* y = (float*)d_out;
    caps_kernel<<<512, 128>>>(x, wt, bs, y);
}

// round 5
// speedup vs baseline: 1.7094x; 1.7094x over previous
#include <cuda_runtime.h>

// CapsuleConvTranspose2d (2,64,32,32) -> (2,64,64,64): stride-2 3x3 transposed
// conv into 8 out-capsules x 8 dims, 3-iter k-means routing, squash, bias.
//
// patch[n,c,kh,kw,p,q] = x[n,c,(p+kh-1)/2,(q+kw-1)/2] iff (p+kh-1) even & in
// range, else 0. Valid kh depends only on parity of p (even->{1}, odd->{0,2});
// same for q/kw. Border taps (p or q = 63, tap 2) are zero-filled: a zero prior
// routes identically (logit 0, exp in Z) and NZEROS covers the rest.
//
// Kernel 1 (prep): transpose x to xt[n][i][j][c] (coalesced main-kernel loads)
// and pack weights per parity class: wpk[cls][(l*8+g)*ntap+tp][m] (float4-able,
// flipped taps baked in).
// Kernel 2: 64 threads per output pixel, g=tid>>3, r=tid&7. Lane r owns the
// ntap priors of tap tp=r%ntap at fields f = r/ntap + k*(8/ntap), fully in
// registers. Routing is register + shuffle (width 8) with recursive-halving
// all-reduce (14 shuffles per 8-vector reduce).

__device__ float g_xt[2 * 32 * 32 * 64];
__device__ __align__(16) float g_wpk[4608];   // cls bases: 0,512,1536,2560

__global__ __launch_bounds__(256)
void prep_kernel(const float* __restrict__ x, const float* __restrict__ wt)
{
    const int b = blockIdx.x;
    const int t = threadIdx.x;
    if (b < 64) {
        // transpose one (n,i) row: x[n][c][i][j] -> xt[n][i][j][c]
        __shared__ float s[64][33];
        const int n = b >> 5, i = b & 31;
        #pragma unroll
        for (int k = 0; k < 8; k++) {
            int idx = t + k * 256;
            int c = idx >> 5, j = idx & 31;
            s[c][j] = x[((n * 64 + c) * 32 + i) * 32 + j];
        }
        __syncthreads();
        #pragma unroll
        for (int k = 0; k < 8; k++) {
            int idx = t + k * 256;
            int j = idx >> 6, c = idx & 63;
            g_xt[((n * 32 + i) * 32 + j) * 64 + c] = s[c][j];
        }
    } else {
        // pack weights: wpk[base + ((l*8+g)*ntap + tp)*8 + m]
        for (int w = t; w < 4608; w += 256) {
            int cls, rem, ntap;
            if (w < 512)       { cls = 0; rem = w;        ntap = 1; }
            else if (w < 1536) { cls = 1; rem = w - 512;  ntap = 2; }
            else if (w < 2560) { cls = 2; rem = w - 1536; ntap = 2; }
            else               { cls = 3; rem = w - 2560; ntap = 4; }
            int m  = rem & 7;
            int e  = rem >> 3;          // (l*8+g)*ntap + tp
            int tp = e % ntap;
            int lg = e / ntap;          // l*8 + g
            int kh, kw;
            if (cls == 0)      { kh = 1;              kw = 1; }
            else if (cls == 1) { kh = 1;              kw = tp << 1; }
            else if (cls == 2) { kh = tp << 1;        kw = 1; }
            else               { kh = (tp >> 1) << 1; kw = (tp & 1) << 1; }
            int woff = (2 - kh) * 3 + (2 - kw);       // flipped kernel tap
            g_wpk[w] = wt[(lg * 8 + m) * 9 + woff];
        }
    }
}

// width-8 all-reduce of an 8-vector: recursive halving + doubling, 14 shuffles
__device__ __forceinline__ void allreduce8(float v[8], int r)
{
    const unsigned FULL = 0xffffffffu;
    const bool b4 = (r & 4) != 0, b2 = (r & 2) != 0, b1 = (r & 1) != 0;
    float w[4], u[2], s;
    #pragma unroll
    for (int i = 0; i < 4; i++) {
        float send = b4 ? v[i] : v[4 + i];
        float keep = b4 ? v[4 + i] : v[i];
        w[i] = keep + __shfl_xor_sync(FULL, send, 4, 8);
    }
    #pragma unroll
    for (int i = 0; i < 2; i++) {
        float send = b2 ? w[i] : w[2 + i];
        float keep = b2 ? w[2 + i] : w[i];
        u[i] = keep + __shfl_xor_sync(FULL, send, 2, 8);
    }
    {
        float send = b1 ? u[0] : u[1];
        float keep = b1 ? u[1] : u[0];
        s = keep + __shfl_xor_sync(FULL, send, 1, 8);   // lane r holds comp r
    }
    float gg = __shfl_xor_sync(FULL, s, 1, 8);
    float p0 = b1 ? gg : s;
    float p1 = b1 ? s : gg;
    float g0 = __shfl_xor_sync(FULL, p0, 2, 8);
    float g1 = __shfl_xor_sync(FULL, p1, 2, 8);
    float qd[4];
    qd[0] = b2 ? g0 : p0;  qd[1] = b2 ? g1 : p1;
    qd[2] = b2 ? p0 : g0;  qd[3] = b2 ? p1 : g1;
    #pragma unroll
    for (int i = 0; i < 4; i++) {
        float gi = __shfl_xor_sync(FULL, qd[i], 4, 8);
        v[i]     = b4 ? gi : qd[i];
        v[4 + i] = b4 ? qd[i] : gi;
    }
}

template<int NKH, int NKW, int BASE>
__device__ __forceinline__ void caps_pixel(
    int n, int p, int q,
    const float* __restrict__ bs, float* __restrict__ y,
    float (*__restrict__ s_x)[72])
{
    constexpr int NTAP  = NKH * NKW;          // 1, 2, 4
    constexpr int CNT   = NTAP;
    constexpr int FSTEP = 8 / NTAP;
    constexpr float NZEROS = (float)(72 - 8 * NTAP);
    const unsigned FULL = 0xffffffffu;

    const int tid = threadIdx.x;
    const int g = tid >> 3;
    const int r = tid & 7;

    // ---- stage x: coalesced from xt; layout s_x[pos][f*9 + l] ----
    #pragma unroll
    for (int pos = 0; pos < NTAP; pos++) {
        int a  = pos / NKW, b = pos % NKW;
        int kh = (NKH == 1) ? 1 : (a << 1);
        int kw = (NKW == 1) ? 1 : (b << 1);
        int i  = (p + kh - 1) >> 1;
        int j  = (q + kw - 1) >> 1;
        bool valid = (i < 32) && (j < 32);    // only tap 2 at p/q == 63 fails
        float v = valid ? g_xt[((n * 32 + i) * 32 + j) * 64 + tid] : 0.f;
        s_x[pos][(tid >> 3) * 9 + (tid & 7)] = v;
    }
    __syncthreads();

    const int tp = r & (NTAP - 1);
    const int f0 = r / NTAP;
    const float* wrow = g_wpk + BASE + (g * NTAP + tp) * 8;
    const float* xrow = s_x[tp] + f0 * 9;

    // ---- priors in registers ----
    float pri[CNT][8];
    #pragma unroll
    for (int k = 0; k < CNT; k++)
        #pragma unroll
        for (int m = 0; m < 8; m++) pri[k][m] = 0.f;

    #pragma unroll
    for (int l = 0; l < 8; l++) {
        float4 w0 = *(const float4*)(wrow + l * (64 * NTAP));
        float4 w1 = *(const float4*)(wrow + l * (64 * NTAP) + 4);
        #pragma unroll
        for (int k = 0; k < CNT; k++) {
            float xv = xrow[k * (FSTEP * 9) + l];
            pri[k][0] = fmaf(xv, w0.x, pri[k][0]);
            pri[k][1] = fmaf(xv, w0.y, pri[k][1]);
            pri[k][2] = fmaf(xv, w0.z, pri[k][2]);
            pri[k][3] = fmaf(xv, w0.w, pri[k][3]);
            pri[k][4] = fmaf(xv, w1.x, pri[k][4]);
            pri[k][5] = fmaf(xv, w1.y, pri[k][5]);
            pri[k][6] = fmaf(xv, w1.z, pri[k][6]);
            pri[k][7] = fmaf(xv, w1.w, pri[k][7]);
        }
    }

    // ---- routing init: mean over all 72 (zeros included in divisor) ----
    float o[8];
    #pragma unroll
    for (int m = 0; m < 8; m++) {
        float s = pri[0][m];
        #pragma unroll
        for (int k = 1; k < CNT; k++) s += pri[k][m];
        o[m] = s;
    }
    allreduce8(o, r);
    #pragma unroll
    for (int m = 0; m < 8; m++) o[m] *= (1.0f / 72.0f);

    #pragma unroll
    for (int it = 0; it < 3; it++) {
        float sn = 0.f;
        #pragma unroll
        for (int m = 0; m < 8; m++) sn = fmaf(o[m], o[m], sn);
        float inv = 1.0f / fmaxf(sqrtf(sn), 1e-12f);

        float lg[CNT];
        float lmax = 0.0f;                    // zero priors pin lmax >= 0
        #pragma unroll
        for (int k = 0; k < CNT; k++) {
            float s = 0.f;
            #pragma unroll
            for (int m = 0; m < 8; m++) s = fmaf(pri[k][m], o[m], s);
            s *= inv;
            lg[k] = s;
            lmax = fmaxf(lmax, s);
        }
        lmax = fmaxf(lmax, __shfl_xor_sync(FULL, lmax, 1, 8));
        lmax = fmaxf(lmax, __shfl_xor_sync(FULL, lmax, 2, 8));
        lmax = fmaxf(lmax, __shfl_xor_sync(FULL, lmax, 4, 8));

        float e[CNT];
        float z = 0.f;
        #pragma unroll
        for (int k = 0; k < CNT; k++) {
            e[k] = __expf(lg[k] - lmax);
            z += e[k];
        }
        z += __shfl_xor_sync(FULL, z, 1, 8);
        z += __shfl_xor_sync(FULL, z, 2, 8);
        z += __shfl_xor_sync(FULL, z, 4, 8);
        z += NZEROS * __expf(-lmax);          // zero-priors' Z share

        float acc[8];
        #pragma unroll
        for (int m = 0; m < 8; m++) acc[m] = e[0] * pri[0][m];
        #pragma unroll
        for (int k = 1; k < CNT; k++)
            #pragma unroll
            for (int m = 0; m < 8; m++)
                acc[m] = fmaf(e[k], pri[k][m], acc[m]);
        allreduce8(acc, r);

        float rz = 1.0f / z;
        #pragma unroll
        for (int m = 0; m < 8; m++) o[m] = acc[m] * rz;
    }

    // ---- squash + bias; lane r writes channel g*8 + r ----
    float sn = 0.f;
    #pragma unroll
    for (int m = 0; m < 8; m++) sn = fmaf(o[m], o[m], sn);
    float scale = sn / ((1.0f + sn) * sqrtf(sn + 1e-12f));
    float val = o[r] * scale + bs[tid];

    y[((n * 64 + tid) * 64 + p) * 64 + q] = val;
}

__global__ __launch_bounds__(64)
void caps_kernel(const float* __restrict__ bs, float* __restrict__ y)
{
    __shared__ float s_x[4][72];

    const int pix = blockIdx.x;
    const int q = pix & 63;
    const int p = (pix >> 6) & 63;
    const int n = pix >> 12;

    const bool po = (p & 1) != 0;
    const bool qo = (q & 1) != 0;

    if (!po && !qo)      caps_pixel<1, 1, 0>(n, p, q, bs, y, s_x);
    else if (!po)        caps_pixel<1, 2, 512>(n, p, q, bs, y, s_x);
    else if (!qo)        caps_pixel<2, 1, 1536>(n, p, q, bs, y, s_x);
    else                 caps_pixel<2, 2, 2560>(n, p, q, bs, y, s_x);
}

extern "C" void kernel_launch(void* const* d_in, const int* in_sizes, int n_in,
                              void* d_out, int out_size) {
    const float* x  = (const float*)d_in[0];
    const float* wt = (const float*)d_in[1];
    const float* bs = (const float*)d_in[2];
    float* y = (float*)d_out;
    prep_kernel<<<65, 256>>>(x, wt);
    caps_kernel<<<2 * 64 * 64, 64>>>(bs, y);
}

// round 6
// speedup vs baseline: 1.8384x; 1.0755x over previous
#include <cuda_runtime.h>

// CapsuleConvTranspose2d (2,64,32,32) -> (2,64,64,64): stride-2 3x3 transposed
// conv into 8 out-capsules x 8 dims, 3-iter k-means routing, squash, bias.
//
// patch[n,c,kh,kw,p,q] = x[n,c,(p+kh-1)/2,(q+kw-1)/2] iff (p+kh-1) even & in
// range, else 0. Valid kh depends only on parity of p (even->{1}, odd->{0,2});
// same for q/kw. Border taps (p or q = 63, tap 2) are zero-filled: a zero prior
// routes identically (contributes 1 to Z), counted in NZEROS.
//
// Softmax is computed WITHOUT max subtraction: logits = (prior . o)/||o|| are
// O(1) here (weights ~0.1 N(0,1)), exp is fp32-safe, and e^x/sum e^x is
// mathematically identical to the max-subtracted form. Zero priors add exactly
// NZEROS to Z.
//
// Kernel 1 (prep): transpose x to xt[n][i][j][c] + pack weights per parity
// class wpk[cls][(l*8+g)*ntap+tp][m] (flipped taps baked in, float4-loadable).
// Kernel 2: 64 threads per pixel, g = tid>>3, r = tid&7. Lane r owns the ntap
// priors of tap tp = r%ntap at fields f = r/ntap + k*(8/ntap), in registers.
// Routing is register + shuffle (width 8); 8-vector all-reduce by recursive
// halving+doubling (14 shfl), final iteration reduce-scatter only (7 shfl).

__device__ float g_xt[2 * 32 * 32 * 64];
__device__ __align__(16) float g_wpk[4608];   // cls bases: 0,512,1536,2560

__global__ __launch_bounds__(256)
void prep_kernel(const float* __restrict__ x, const float* __restrict__ wt)
{
    const int b = blockIdx.x;
    const int t = threadIdx.x;
    if (b < 128) {
        // transpose half the channels of one (n,i) row: x[n][c][i][j] -> xt[n][i][j][c]
        __shared__ float s[32][33];
        const int n  = b >> 6;
        const int i  = (b >> 1) & 31;
        const int ch = (b & 1) << 5;
        #pragma unroll
        for (int k = 0; k < 4; k++) {
            int idx = t + k * 256;
            int c = idx >> 5, j = idx & 31;
            s[c][j] = x[((n * 64 + ch + c) * 32 + i) * 32 + j];
        }
        __syncthreads();
        #pragma unroll
        for (int k = 0; k < 4; k++) {
            int idx = t + k * 256;
            int j = idx >> 5, c = idx & 31;
            g_xt[((n * 32 + i) * 32 + j) * 64 + ch + c] = s[c][j];
        }
    } else {
        // pack weights: wpk[base + ((l*8+g)*ntap + tp)*8 + m]
        for (int w = t; w < 4608; w += 256) {
            int cls, rem, ntap;
            if (w < 512)       { cls = 0; rem = w;        ntap = 1; }
            else if (w < 1536) { cls = 1; rem = w - 512;  ntap = 2; }
            else if (w < 2560) { cls = 2; rem = w - 1536; ntap = 2; }
            else               { cls = 3; rem = w - 2560; ntap = 4; }
            int m  = rem & 7;
            int e  = rem >> 3;          // (l*8+g)*ntap + tp
            int tp = e % ntap;
            int lg = e / ntap;          // l*8 + g
            int kh, kw;
            if (cls == 0)      { kh = 1;              kw = 1; }
            else if (cls == 1) { kh = 1;              kw = tp << 1; }
            else if (cls == 2) { kh = tp << 1;        kw = 1; }
            else               { kh = (tp >> 1) << 1; kw = (tp & 1) << 1; }
            int woff = (2 - kh) * 3 + (2 - kw);       // flipped kernel tap
            g_wpk[w] = wt[(lg * 8 + m) * 9 + woff];
        }
    }
}

// reduce-scatter over width 8: returns the fully-summed component r (7 shfl)
__device__ __forceinline__ float reduce_scatter8(const float v[8], int r)
{
    const unsigned FULL = 0xffffffffu;
    const bool b4 = (r & 4) != 0, b2 = (r & 2) != 0, b1 = (r & 1) != 0;
    float w[4], u[2];
    #pragma unroll
    for (int i = 0; i < 4; i++) {
        float send = b4 ? v[i] : v[4 + i];
        float keep = b4 ? v[4 + i] : v[i];
        w[i] = keep + __shfl_xor_sync(FULL, send, 4, 8);
    }
    #pragma unroll
    for (int i = 0; i < 2; i++) {
        float send = b2 ? w[i] : w[2 + i];
        float keep = b2 ? w[2 + i] : w[i];
        u[i] = keep + __shfl_xor_sync(FULL, send, 2, 8);
    }
    float send = b1 ? u[0] : u[1];
    float keep = b1 ? u[1] : u[0];
    return keep + __shfl_xor_sync(FULL, send, 1, 8);
}

// width-8 all-reduce of an 8-vector: halving + doubling, 14 shuffles
__device__ __forceinline__ void allreduce8(float v[8], int r)
{
    const unsigned FULL = 0xffffffffu;
    const bool b4 = (r & 4) != 0, b2 = (r & 2) != 0, b1 = (r & 1) != 0;
    float s = reduce_scatter8(v, r);
    float gg = __shfl_xor_sync(FULL, s, 1, 8);
    float p0 = b1 ? gg : s;
    float p1 = b1 ? s : gg;
    float g0 = __shfl_xor_sync(FULL, p0, 2, 8);
    float g1 = __shfl_xor_sync(FULL, p1, 2, 8);
    float qd[4];
    qd[0] = b2 ? g0 : p0;  qd[1] = b2 ? g1 : p1;
    qd[2] = b2 ? p0 : g0;  qd[3] = b2 ? p1 : g1;
    #pragma unroll
    for (int i = 0; i < 4; i++) {
        float gi = __shfl_xor_sync(FULL, qd[i], 4, 8);
        v[i]     = b4 ? gi : qd[i];
        v[4 + i] = b4 ? qd[i] : gi;
    }
}

template<int NKH, int NKW, int BASE>
__device__ __forceinline__ void caps_pixel(
    int n, int p, int q,
    const float* __restrict__ bs, float* __restrict__ y,
    float (*__restrict__ s_x)[64])
{
    constexpr int NTAP  = NKH * NKW;          // 1, 2, 4
    constexpr int CNT   = NTAP;
    constexpr float NZEROS = (float)(72 - 8 * NTAP);
    const unsigned FULL = 0xffffffffu;

    const int tid = threadIdx.x;
    const int g = tid >> 3;
    const int r = tid & 7;

    // ---- stage x: coalesced from xt; layout s_x[pos][c] (c = f*8 + l) ----
    #pragma unroll
    for (int pos = 0; pos < NTAP; pos++) {
        int a  = pos / NKW, b = pos % NKW;
        int kh = (NKH == 1) ? 1 : (a << 1);
        int kw = (NKW == 1) ? 1 : (b << 1);
        int i  = (p + kh - 1) >> 1;
        int j  = (q + kw - 1) >> 1;
        bool valid = (i < 32) && (j < 32);    // only tap 2 at p/q == 63 fails
        s_x[pos][tid] = valid ? g_xt[((n * 32 + i) * 32 + j) * 64 + tid] : 0.f;
    }
    __syncthreads();

    const int tp = r & (NTAP - 1);
    const int f0 = r / NTAP;
    const float* wrow = g_wpk + BASE + (g * NTAP + tp) * 8;
    const float* xrow = s_x[tp] + f0 * 8;

    // ---- priors in registers ----
    float pri[CNT][8];
    #pragma unroll
    for (int k = 0; k < CNT; k++)
        #pragma unroll
        for (int m = 0; m < 8; m++) pri[k][m] = 0.f;

    if (NTAP <= 2) {
        // preload lane's x as float4s (8 floats per owned prior)
        float xr[CNT][8];
        #pragma unroll
        for (int k = 0; k < CNT; k++) {
            // field f = f0 + k*(8/NTAP)  ->  offset (8/NTAP)*8*k floats
            float4 u0 = *(const float4*)(xrow + k * (8 / NTAP) * 8);
            float4 u1 = *(const float4*)(xrow + k * (8 / NTAP) * 8 + 4);
            xr[k][0] = u0.x; xr[k][1] = u0.y; xr[k][2] = u0.z; xr[k][3] = u0.w;
            xr[k][4] = u1.x; xr[k][5] = u1.y; xr[k][6] = u1.z; xr[k][7] = u1.w;
        }
        #pragma unroll
        for (int l = 0; l < 8; l++) {
            float4 w0 = *(const float4*)(wrow + l * (64 * NTAP));
            float4 w1 = *(const float4*)(wrow + l * (64 * NTAP) + 4);
            #pragma unroll
            for (int k = 0; k < CNT; k++) {
                float xv = xr[k][l];
                pri[k][0] = fmaf(xv, w0.x, pri[k][0]);
                pri[k][1] = fmaf(xv, w0.y, pri[k][1]);
                pri[k][2] = fmaf(xv, w0.z, pri[k][2]);
                pri[k][3] = fmaf(xv, w0.w, pri[k][3]);
                pri[k][4] = fmaf(xv, w1.x, pri[k][4]);
                pri[k][5] = fmaf(xv, w1.y, pri[k][5]);
                pri[k][6] = fmaf(xv, w1.z, pri[k][6]);
                pri[k][7] = fmaf(xv, w1.w, pri[k][7]);
            }
        }
    } else {
        // NTAP == 4: float2 x reads (no register blowup), l in pairs
        #pragma unroll
        for (int l2 = 0; l2 < 4; l2++) {
            const int l = l2 * 2;
            float4 wA0 = *(const float4*)(wrow + l * 256);
            float4 wA1 = *(const float4*)(wrow + l * 256 + 4);
            float4 wB0 = *(const float4*)(wrow + (l + 1) * 256);
            float4 wB1 = *(const float4*)(wrow + (l + 1) * 256 + 4);
            #pragma unroll
            for (int k = 0; k < 4; k++) {
                float2 xv = *(const float2*)(xrow + k * 16 + l);  // f = f0 + 2k
                pri[k][0] = fmaf(xv.x, wA0.x, pri[k][0]);
                pri[k][1] = fmaf(xv.x, wA0.y, pri[k][1]);
                pri[k][2] = fmaf(xv.x, wA0.z, pri[k][2]);
                pri[k][3] = fmaf(xv.x, wA0.w, pri[k][3]);
                pri[k][4] = fmaf(xv.x, wA1.x, pri[k][4]);
                pri[k][5] = fmaf(xv.x, wA1.y, pri[k][5]);
                pri[k][6] = fmaf(xv.x, wA1.z, pri[k][6]);
                pri[k][7] = fmaf(xv.x, wA1.w, pri[k][7]);
                pri[k][0] = fmaf(xv.y, wB0.x, pri[k][0]);
                pri[k][1] = fmaf(xv.y, wB0.y, pri[k][1]);
                pri[k][2] = fmaf(xv.y, wB0.z, pri[k][2]);
                pri[k][3] = fmaf(xv.y, wB0.w, pri[k][3]);
                pri[k][4] = fmaf(xv.y, wB1.x, pri[k][4]);
                pri[k][5] = fmaf(xv.y, wB1.y, pri[k][5]);
                pri[k][6] = fmaf(xv.y, wB1.z, pri[k][6]);
                pri[k][7] = fmaf(xv.y, wB1.w, pri[k][7]);
            }
        }
    }

    // ---- routing init: mean over all 72 (zeros included in divisor) ----
    float o[8];
    #pragma unroll
    for (int m = 0; m < 8; m++) {
        float s = pri[0][m];
        #pragma unroll
        for (int k = 1; k < CNT; k++) s += pri[k][m];
        o[m] = s;
    }
    allreduce8(o, r);
    #pragma unroll
    for (int m = 0; m < 8; m++) o[m] *= (1.0f / 72.0f);

    // ---- iterations 0,1: full all-reduce ----
    #pragma unroll
    for (int it = 0; it < 2; it++) {
        float sn = 0.f;
        #pragma unroll
        for (int m = 0; m < 8; m++) sn = fmaf(o[m], o[m], sn);
        float inv = rsqrtf(fmaxf(sn, 1e-24f));

        float e[CNT];
        float z = 0.f;
        #pragma unroll
        for (int k = 0; k < CNT; k++) {
            float s = 0.f;
            #pragma unroll
            for (int m = 0; m < 8; m++) s = fmaf(pri[k][m], o[m], s);
            e[k] = __expf(s * inv);
            z += e[k];
        }
        z += __shfl_xor_sync(FULL, z, 1, 8);
        z += __shfl_xor_sync(FULL, z, 2, 8);
        z += __shfl_xor_sync(FULL, z, 4, 8);
        z += NZEROS;                           // zero-priors: exp(0) each

        float acc[8];
        #pragma unroll
        for (int m = 0; m < 8; m++) acc[m] = e[0] * pri[0][m];
        #pragma unroll
        for (int k = 1; k < CNT; k++)
            #pragma unroll
            for (int m = 0; m < 8; m++)
                acc[m] = fmaf(e[k], pri[k][m], acc[m]);
        allreduce8(acc, r);

        float rz = __fdividef(1.0f, z);
        #pragma unroll
        for (int m = 0; m < 8; m++) o[m] = acc[m] * rz;
    }

    // ---- final iteration: reduce-scatter only (lane r needs component r) ----
    {
        float sn = 0.f;
        #pragma unroll
        for (int m = 0; m < 8; m++) sn = fmaf(o[m], o[m], sn);
        float inv = rsqrtf(fmaxf(sn, 1e-24f));

        float e[CNT];
        float z = 0.f;
        #pragma unroll
        for (int k = 0; k < CNT; k++) {
            float s = 0.f;
            #pragma unroll
            for (int m = 0; m < 8; m++) s = fmaf(pri[k][m], o[m], s);
            e[k] = __expf(s * inv);
            z += e[k];
        }
        z += __shfl_xor_sync(FULL, z, 1, 8);
        z += __shfl_xor_sync(FULL, z, 2, 8);
        z += __shfl_xor_sync(FULL, z, 4, 8);
        z += NZEROS;

        float acc[8];
        #pragma unroll
        for (int m = 0; m < 8; m++) acc[m] = e[0] * pri[0][m];
        #pragma unroll
        for (int k = 1; k < CNT; k++)
            #pragma unroll
            for (int m = 0; m < 8; m++)
                acc[m] = fmaf(e[k], pri[k][m], acc[m]);

        float s   = reduce_scatter8(acc, r);      // component r, fully summed
        float orr = s * __fdividef(1.0f, z);

        float sq = orr * orr;                      // ||o||^2 via 3 shuffles
        sq += __shfl_xor_sync(FULL, sq, 1, 8);
        sq += __shfl_xor_sync(FULL, sq, 2, 8);
        sq += __shfl_xor_sync(FULL, sq, 4, 8);

        float scale = sq / ((1.0f + sq) * sqrtf(sq + 1e-12f));
        y[((n * 64 + tid) * 64 + p) * 64 + q] = orr * scale + bs[tid];
    }
}

__global__ __launch_bounds__(64)
void caps_kernel(const float* __restrict__ bs, float* __restrict__ y)
{
    __shared__ float s_x[4][64];

    const int pix = blockIdx.x;
    const int q = pix & 63;
    const int p = (pix >> 6) & 63;
    const int n = pix >> 12;

    const bool po = (p & 1) != 0;
    const bool qo = (q & 1) != 0;

    if (!po && !qo)      caps_pixel<1, 1, 0>(n, p, q, bs, y, s_x);
    else if (!po)        caps_pixel<1, 2, 512>(n, p, q, bs, y, s_x);
    else if (!qo)        caps_pixel<2, 1, 1536>(n, p, q, bs, y, s_x);
    else                 caps_pixel<2, 2, 2560>(n, p, q, bs, y, s_x);
}

extern "C" void kernel_launch(void* const* d_in, const int* in_sizes, int n_in,
                              void* d_out, int out_size) {
    const float* x  = (const float*)d_in[0];
    const float* wt = (const float*)d_in[1];
    const float* bs = (const float*)d_in[2];
    float* y = (float*)d_out;
    prep_kernel<<<129, 256>>>(x, wt);
    caps_kernel<<<2 * 64 * 64, 64>>>(bs, y);
}

// round 7
// speedup vs baseline: 1.9911x; 1.0830x over previous
#include <cuda_runtime.h>

// CapsuleConvTranspose2d (2,64,32,32) -> (2,64,64,64): stride-2 3x3 transposed
// conv into 8 out-capsules x 8 dims, 3-iter k-means routing, squash, bias.
//
// patch[n,c,kh,kw,p,q] = x[n,c,(p+kh-1)/2,(q+kw-1)/2] iff (p+kh-1) even & in
// range, else 0. Valid kh depends only on parity of p (even->{1}, odd->{0,2});
// same for q/kw. Border taps (p or q = 63, tap 2) are zero-filled: a zero prior
// routes identically (contributes exp(0)=1 to Z), counted in NZEROS.
//
// Softmax without max subtraction: logits = (prior . o)/||o|| are O(1) here,
// exp is fp32-safe, e^x/sum e^x identical to the subtracted form; zero priors
// add exactly NZEROS to Z.
//
// Kernel 1 (prep): transpose x -> xt[n][i][j][c]; pack weights per parity
// class: wpk[cls][(l*8+g)*ntap+tp][m], flipped taps baked in (float4 loads).
// Kernel 2: 64 threads per pixel, g = tid>>3, r = tid&7. Lane r owns the ntap
// priors of tap tp at fields f0 + k*(8/ntap), in registers.
//   EE/EO/OE: x read directly from xt into registers (contiguous 32B per
//   field, broadcast across capsule groups) - no smem, no block sync.
//   OO: x staged once in smem, pitch-9 layout (conflict-free scalar LDS).
// Routing: register + width-8 shuffles; 8-vector all-reduce via recursive
// halving+doubling (14 shfl); final iteration reduce-scatter only (7 shfl).

__device__ float g_xt[2 * 32 * 32 * 64];
__device__ __align__(16) float g_wpk[4608];   // cls bases: 0,512,1536,2560

__global__ __launch_bounds__(256)
void prep_kernel(const float* __restrict__ x, const float* __restrict__ wt)
{
    const int b = blockIdx.x;
    const int t = threadIdx.x;
    if (b < 128) {
        // transpose half the channels of one (n,i) row: x[n][c][i][j] -> xt[n][i][j][c]
        __shared__ float s[32][33];
        const int n  = b >> 6;
        const int i  = (b >> 1) & 31;
        const int ch = (b & 1) << 5;
        #pragma unroll
        for (int k = 0; k < 4; k++) {
            int idx = t + k * 256;
            int c = idx >> 5, j = idx & 31;
            s[c][j] = x[((n * 64 + ch + c) * 32 + i) * 32 + j];
        }
        __syncthreads();
        #pragma unroll
        for (int k = 0; k < 4; k++) {
            int idx = t + k * 256;
            int j = idx >> 5, c = idx & 31;
            g_xt[((n * 32 + i) * 32 + j) * 64 + ch + c] = s[c][j];
        }
    } else {
        // pack weights: wpk[base + ((l*8+g)*ntap + tp)*8 + m]
        for (int w = t; w < 4608; w += 256) {
            int cls, rem, ntap;
            if (w < 512)       { cls = 0; rem = w;        ntap = 1; }
            else if (w < 1536) { cls = 1; rem = w - 512;  ntap = 2; }
            else if (w < 2560) { cls = 2; rem = w - 1536; ntap = 2; }
            else               { cls = 3; rem = w - 2560; ntap = 4; }
            int m  = rem & 7;
            int e  = rem >> 3;          // (l*8+g)*ntap + tp
            int tp = e % ntap;
            int lg = e / ntap;          // l*8 + g
            int kh, kw;
            if (cls == 0)      { kh = 1;              kw = 1; }
            else if (cls == 1) { kh = 1;              kw = tp << 1; }
            else if (cls == 2) { kh = tp << 1;        kw = 1; }
            else               { kh = (tp >> 1) << 1; kw = (tp & 1) << 1; }
            int woff = (2 - kh) * 3 + (2 - kw);       // flipped kernel tap
            g_wpk[w] = wt[(lg * 8 + m) * 9 + woff];
        }
    }
}

// reduce-scatter over width 8: returns fully-summed component r (7 shfl)
__device__ __forceinline__ float reduce_scatter8(const float v[8], int r)
{
    const unsigned FULL = 0xffffffffu;
    const bool b4 = (r & 4) != 0, b2 = (r & 2) != 0, b1 = (r & 1) != 0;
    float w[4], u[2];
    #pragma unroll
    for (int i = 0; i < 4; i++) {
        float send = b4 ? v[i] : v[4 + i];
        float keep = b4 ? v[4 + i] : v[i];
        w[i] = keep + __shfl_xor_sync(FULL, send, 4, 8);
    }
    #pragma unroll
    for (int i = 0; i < 2; i++) {
        float send = b2 ? w[i] : w[2 + i];
        float keep = b2 ? w[2 + i] : w[i];
        u[i] = keep + __shfl_xor_sync(FULL, send, 2, 8);
    }
    float send = b1 ? u[0] : u[1];
    float keep = b1 ? u[1] : u[0];
    return keep + __shfl_xor_sync(FULL, send, 1, 8);
}

// width-8 all-reduce of an 8-vector: halving + doubling, 14 shuffles
__device__ __forceinline__ void allreduce8(float v[8], int r)
{
    const unsigned FULL = 0xffffffffu;
    const bool b4 = (r & 4) != 0, b2 = (r & 2) != 0, b1 = (r & 1) != 0;
    float s = reduce_scatter8(v, r);
    float gg = __shfl_xor_sync(FULL, s, 1, 8);
    float p0 = b1 ? gg : s;
    float p1 = b1 ? s : gg;
    float g0 = __shfl_xor_sync(FULL, p0, 2, 8);
    float g1 = __shfl_xor_sync(FULL, p1, 2, 8);
    float qd[4];
    qd[0] = b2 ? g0 : p0;  qd[1] = b2 ? g1 : p1;
    qd[2] = b2 ? p0 : g0;  qd[3] = b2 ? p1 : g1;
    #pragma unroll
    for (int i = 0; i < 4; i++) {
        float gi = __shfl_xor_sync(FULL, qd[i], 4, 8);
        v[i]     = b4 ? gi : qd[i];
        v[4 + i] = b4 ? qd[i] : gi;
    }
}

// routing + squash + store; priors live in pri[CNT][8]
template<int CNT>
__device__ __forceinline__ void route_and_store(
    float pri[CNT][8], int n, int p, int q,
    const float* __restrict__ bs, float* __restrict__ y)
{
    constexpr float NZEROS = (float)(72 - 8 * CNT);
    const unsigned FULL = 0xffffffffu;
    const int tid = threadIdx.x;
    const int r = tid & 7;

    // init: mean over all 72 (zeros included in divisor)
    float o[8];
    #pragma unroll
    for (int m = 0; m < 8; m++) {
        float s = pri[0][m];
        #pragma unroll
        for (int k = 1; k < CNT; k++) s += pri[k][m];
        o[m] = s;
    }
    allreduce8(o, r);
    #pragma unroll
    for (int m = 0; m < 8; m++) o[m] *= (1.0f / 72.0f);

    #pragma unroll
    for (int it = 0; it < 2; it++) {
        float sn = 0.f;
        #pragma unroll
        for (int m = 0; m < 8; m++) sn = fmaf(o[m], o[m], sn);
        float inv = rsqrtf(fmaxf(sn, 1e-24f));

        float e[CNT];
        float z = 0.f;
        #pragma unroll
        for (int k = 0; k < CNT; k++) {
            float s = 0.f;
            #pragma unroll
            for (int m = 0; m < 8; m++) s = fmaf(pri[k][m], o[m], s);
            e[k] = __expf(s * inv);
            z += e[k];
        }
        z += __shfl_xor_sync(FULL, z, 1, 8);
        z += __shfl_xor_sync(FULL, z, 2, 8);
        z += __shfl_xor_sync(FULL, z, 4, 8);
        z += NZEROS;

        float acc[8];
        #pragma unroll
        for (int m = 0; m < 8; m++) acc[m] = e[0] * pri[0][m];
        #pragma unroll
        for (int k = 1; k < CNT; k++)
            #pragma unroll
            for (int m = 0; m < 8; m++)
                acc[m] = fmaf(e[k], pri[k][m], acc[m]);
        allreduce8(acc, r);

        float rz = __fdividef(1.0f, z);
        #pragma unroll
        for (int m = 0; m < 8; m++) o[m] = acc[m] * rz;
    }

    // final iteration: reduce-scatter only (lane r keeps component r)
    float sn = 0.f;
    #pragma unroll
    for (int m = 0; m < 8; m++) sn = fmaf(o[m], o[m], sn);
    float inv = rsqrtf(fmaxf(sn, 1e-24f));

    float e[CNT];
    float z = 0.f;
    #pragma unroll
    for (int k = 0; k < CNT; k++) {
        float s = 0.f;
        #pragma unroll
        for (int m = 0; m < 8; m++) s = fmaf(pri[k][m], o[m], s);
        e[k] = __expf(s * inv);
        z += e[k];
    }
    z += __shfl_xor_sync(FULL, z, 1, 8);
    z += __shfl_xor_sync(FULL, z, 2, 8);
    z += __shfl_xor_sync(FULL, z, 4, 8);
    z += NZEROS;

    float acc[8];
    #pragma unroll
    for (int m = 0; m < 8; m++) acc[m] = e[0] * pri[0][m];
    #pragma unroll
    for (int k = 1; k < CNT; k++)
        #pragma unroll
        for (int m = 0; m < 8; m++)
            acc[m] = fmaf(e[k], pri[k][m], acc[m]);

    float s   = reduce_scatter8(acc, r);
    float orr = s * __fdividef(1.0f, z);

    float sq = orr * orr;
    sq += __shfl_xor_sync(FULL, sq, 1, 8);
    sq += __shfl_xor_sync(FULL, sq, 2, 8);
    sq += __shfl_xor_sync(FULL, sq, 4, 8);

    float scale = sq / ((1.0f + sq) * sqrtf(sq + 1e-12f));
    y[((n * 64 + tid) * 64 + p) * 64 + q] = orr * scale + bs[tid];
}

__device__ __forceinline__ void load8(float dst[8], const float* src, bool valid)
{
    if (valid) {
        float4 u0 = *(const float4*)(src);
        float4 u1 = *(const float4*)(src + 4);
        dst[0] = u0.x; dst[1] = u0.y; dst[2] = u0.z; dst[3] = u0.w;
        dst[4] = u1.x; dst[5] = u1.y; dst[6] = u1.z; dst[7] = u1.w;
    } else {
        #pragma unroll
        for (int i = 0; i < 8; i++) dst[i] = 0.f;
    }
}

// NTAP<=2 classes: x direct from g_xt (registers), weights float4 from g_wpk.
template<int NTAP, int BASE>
__device__ __forceinline__ void caps_direct(
    int n, int p, int q, int i0, int j0, bool ivar,   // ivar: tap varies i (OE)
    const float* __restrict__ bs, float* __restrict__ y)
{
    const int tid = threadIdx.x;
    const int g = tid >> 3;
    const int r = tid & 7;
    const int tp = r & (NTAP - 1);
    const int f0 = r / NTAP;

    // lane's x rows
    float xr[NTAP][8];   // [k][l], fields f0 + k*(8/NTAP)
    if (NTAP == 1) {
        const float* xb = g_xt + ((n * 32 + i0) * 32 + j0) * 64 + f0 * 8;
        load8(xr[0], xb, true);
    } else {
        int i = ivar ? (i0 + tp) : i0;
        int j = ivar ? j0 : (j0 + tp);
        bool valid = (i < 32) && (j < 32);     // tap 2 at p/q == 63
        const float* xb = g_xt + ((n * 32 + i) * 32 + j) * 64;
        load8(xr[0], xb + f0 * 8, valid);
        load8(xr[1], xb + (f0 + 4) * 8, valid);
    }

    const float* wrow = g_wpk + BASE + (g * NTAP + tp) * 8;

    float pri[NTAP][8];
    #pragma unroll
    for (int k = 0; k < NTAP; k++)
        #pragma unroll
        for (int m = 0; m < 8; m++) pri[k][m] = 0.f;

    #pragma unroll
    for (int l = 0; l < 8; l++) {
        float4 w0 = *(const float4*)(wrow + l * (64 * NTAP));
        float4 w1 = *(const float4*)(wrow + l * (64 * NTAP) + 4);
        #pragma unroll
        for (int k = 0; k < NTAP; k++) {
            float xv = xr[k][l];
            pri[k][0] = fmaf(xv, w0.x, pri[k][0]);
            pri[k][1] = fmaf(xv, w0.y, pri[k][1]);
            pri[k][2] = fmaf(xv, w0.z, pri[k][2]);
            pri[k][3] = fmaf(xv, w0.w, pri[k][3]);
            pri[k][4] = fmaf(xv, w1.x, pri[k][4]);
            pri[k][5] = fmaf(xv, w1.y, pri[k][5]);
            pri[k][6] = fmaf(xv, w1.z, pri[k][6]);
            pri[k][7] = fmaf(xv, w1.w, pri[k][7]);
        }
    }

    route_and_store<NTAP>(pri, n, p, q, bs, y);
}

// OO class: x staged in smem pitch-9 (conflict-free), scalar LDS reads.
__device__ __forceinline__ void caps_oo(
    int n, int p, int q, float* __restrict__ s_x,
    const float* __restrict__ bs, float* __restrict__ y)
{
    const int tid = threadIdx.x;
    const int g = tid >> 3;
    const int r = tid & 7;

    const int i0 = p >> 1, j0 = q >> 1;   // p,q odd: (p-1)/2
    // stage: s_x[pos*72 + f*9 + l], pos = a*2+b
    #pragma unroll
    for (int pos = 0; pos < 4; pos++) {
        int i = i0 + (pos >> 1);
        int j = j0 + (pos & 1);
        bool valid = (i < 32) && (j < 32);
        float v = valid ? g_xt[((n * 32 + i) * 32 + j) * 64 + tid] : 0.f;
        s_x[pos * 72 + (tid >> 3) * 9 + (tid & 7)] = v;
    }
    __syncthreads();

    const int tp = r & 3;
    const int f0 = r >> 2;
    const float* wrow = g_wpk + 2560 + (g * 4 + tp) * 8;
    const float* xrow = s_x + tp * 72 + f0 * 9;   // field f0+2k -> + k*18

    float pri[4][8];
    #pragma unroll
    for (int k = 0; k < 4; k++)
        #pragma unroll
        for (int m = 0; m < 8; m++) pri[k][m] = 0.f;

    #pragma unroll
    for (int l = 0; l < 8; l++) {
        float4 w0 = *(const float4*)(wrow + l * 256);
        float4 w1 = *(const float4*)(wrow + l * 256 + 4);
        #pragma unroll
        for (int k = 0; k < 4; k++) {
            float xv = xrow[k * 18 + l];
            pri[k][0] = fmaf(xv, w0.x, pri[k][0]);
            pri[k][1] = fmaf(xv, w0.y, pri[k][1]);
            pri[k][2] = fmaf(xv, w0.z, pri[k][2]);
            pri[k][3] = fmaf(xv, w0.w, pri[k][3]);
            pri[k][4] = fmaf(xv, w1.x, pri[k][4]);
            pri[k][5] = fmaf(xv, w1.y, pri[k][5]);
            pri[k][6] = fmaf(xv, w1.z, pri[k][6]);
            pri[k][7] = fmaf(xv, w1.w, pri[k][7]);
        }
    }

    route_and_store<4>(pri, n, p, q, bs, y);
}

__global__ __launch_bounds__(64, 16)
void caps_kernel(const float* __restrict__ bs, float* __restrict__ y)
{
    __shared__ float s_x[4 * 72];

    const int pix = blockIdx.x;
    const int q = pix & 63;
    const int p = (pix >> 6) & 63;
    const int n = pix >> 12;

    const bool po = (p & 1) != 0;
    const bool qo = (q & 1) != 0;

    if (!po && !qo)
        caps_direct<1, 0>(n, p, q, p >> 1, q >> 1, false, bs, y);
    else if (!po)
        caps_direct<2, 512>(n, p, q, p >> 1, q >> 1, false, bs, y);   // j = j0+tp
    else if (!qo)
        caps_direct<2, 1536>(n, p, q, p >> 1, q >> 1, true, bs, y);   // i = i0+tp
    else
        caps_oo(n, p, q, s_x, bs, y);
}

extern "C" void kernel_launch(void* const* d_in, const int* in_sizes, int n_in,
                              void* d_out, int out_size) {
    const float* x  = (const float*)d_in[0];
    const float* wt = (const float*)d_in[1];
    const float* bs = (const float*)d_in[2];
    float* y = (float*)d_out;
    prep_kernel<<<129, 256>>>(x, wt);
    caps_kernel<<<2 * 64 * 64, 64>>>(bs, y);
}

// round 8
// speedup vs baseline: 2.1683x; 1.0890x over previous
#include <cuda_runtime.h>

// CapsuleConvTranspose2d (2,64,32,32) -> (2,64,64,64): stride-2 3x3 transposed
// conv into 8 out-capsules x 8 dims, 3-iter k-means routing, squash, bias.
//
// patch[n,c,kh,kw,p,q] = x[n,c,(p+kh-1)/2,(q+kw-1)/2] iff (p+kh-1) even & in
// range, else 0. Valid kh depends only on parity of p (even->{1}, odd->{0,2});
// same for q/kw. Border taps (p or q = 63, tap 2) are zero-filled: a zero prior
// routes identically (contributes exp(0)=1 to Z), counted in NZEROS.
//
// Softmax without max subtraction (logits O(1) here, fp32-safe); zero priors
// add exactly NZEROS to Z.
//
// All 8-dim vector math uses packed f32x2 FMA (SASS FFMA2 via PTX
// fma.rn.f32x2): priors, logits, weighted sums run on register pairs
// (m0,m1)(m2,m3)(m4,m5)(m6,m7); reductions/shuffles stay scalar fp32.
//
// Kernel 1 (prep): transpose x -> xt[n][i][j][c]; pack weights per parity
// class wpk[cls][(l*8+g)*ntap+tp][m] (flipped taps baked in, ulonglong2 loads).
// Kernel 2: 64 threads per pixel, g=tid>>3, r=tid&7; lane r owns the ntap
// priors of tap tp at fields f0 + k*(8/ntap), in registers. EE/EO/OE read x
// directly from xt (no smem/sync); OO stages x in smem pitch-9 (conflict-free).

typedef unsigned long long ull;

__device__ __forceinline__ ull pack2(float lo, float hi) {
    ull r; asm("mov.b64 %0,{%1,%2};" : "=l"(r) : "f"(lo), "f"(hi)); return r;
}
__device__ __forceinline__ void unpack2(ull v, float& lo, float& hi) {
    asm("mov.b64 {%0,%1},%2;" : "=f"(lo), "=f"(hi) : "l"(v));
}
__device__ __forceinline__ ull fma2(ull a, ull b, ull c) {
    ull d; asm("fma.rn.f32x2 %0,%1,%2,%3;" : "=l"(d) : "l"(a), "l"(b), "l"(c)); return d;
}
__device__ __forceinline__ ull mul2(ull a, ull b) {
    ull d; asm("mul.rn.f32x2 %0,%1,%2;" : "=l"(d) : "l"(a), "l"(b)); return d;
}
__device__ __forceinline__ ull add2(ull a, ull b) {
    ull d; asm("add.rn.f32x2 %0,%1,%2;" : "=l"(d) : "l"(a), "l"(b)); return d;
}

__device__ float g_xt[2 * 32 * 32 * 64];
__device__ __align__(16) float g_wpk[4608];   // cls bases: 0,512,1536,2560

__global__ __launch_bounds__(256)
void prep_kernel(const float* __restrict__ x, const float* __restrict__ wt)
{
    const int b = blockIdx.x;
    const int t = threadIdx.x;
    if (b < 128) {
        // transpose half the channels of one (n,i) row: x[n][c][i][j] -> xt[n][i][j][c]
        __shared__ float s[32][33];
        const int n  = b >> 6;
        const int i  = (b >> 1) & 31;
        const int ch = (b & 1) << 5;
        #pragma unroll
        for (int k = 0; k < 4; k++) {
            int idx = t + k * 256;
            int c = idx >> 5, j = idx & 31;
            s[c][j] = x[((n * 64 + ch + c) * 32 + i) * 32 + j];
        }
        __syncthreads();
        #pragma unroll
        for (int k = 0; k < 4; k++) {
            int idx = t + k * 256;
            int j = idx >> 5, c = idx & 31;
            g_xt[((n * 32 + i) * 32 + j) * 64 + ch + c] = s[c][j];
        }
    } else {
        // pack weights: wpk[base + ((l*8+g)*ntap + tp)*8 + m]
        for (int w = t; w < 4608; w += 256) {
            int cls, rem, ntap;
            if (w < 512)       { cls = 0; rem = w;        ntap = 1; }
            else if (w < 1536) { cls = 1; rem = w - 512;  ntap = 2; }
            else if (w < 2560) { cls = 2; rem = w - 1536; ntap = 2; }
            else               { cls = 3; rem = w - 2560; ntap = 4; }
            int m  = rem & 7;
            int e  = rem >> 3;          // (l*8+g)*ntap + tp
            int tp = e % ntap;
            int lg = e / ntap;          // l*8 + g
            int kh, kw;
            if (cls == 0)      { kh = 1;              kw = 1; }
            else if (cls == 1) { kh = 1;              kw = tp << 1; }
            else if (cls == 2) { kh = tp << 1;        kw = 1; }
            else               { kh = (tp >> 1) << 1; kw = (tp & 1) << 1; }
            int woff = (2 - kh) * 3 + (2 - kw);       // flipped kernel tap
            g_wpk[w] = wt[(lg * 8 + m) * 9 + woff];
        }
    }
}

// reduce-scatter over width 8: returns fully-summed component r (7 shfl)
__device__ __forceinline__ float reduce_scatter8(const float v[8], int r)
{
    const unsigned FULL = 0xffffffffu;
    const bool b4 = (r & 4) != 0, b2 = (r & 2) != 0, b1 = (r & 1) != 0;
    float w[4], u[2];
    #pragma unroll
    for (int i = 0; i < 4; i++) {
        float send = b4 ? v[i] : v[4 + i];
        float keep = b4 ? v[4 + i] : v[i];
        w[i] = keep + __shfl_xor_sync(FULL, send, 4, 8);
    }
    #pragma unroll
    for (int i = 0; i < 2; i++) {
        float send = b2 ? w[i] : w[2 + i];
        float keep = b2 ? w[2 + i] : w[i];
        u[i] = keep + __shfl_xor_sync(FULL, send, 2, 8);
    }
    float send = b1 ? u[0] : u[1];
    float keep = b1 ? u[1] : u[0];
    return keep + __shfl_xor_sync(FULL, send, 1, 8);
}

// width-8 all-reduce of an 8-vector: halving + doubling, 14 shuffles
__device__ __forceinline__ void allreduce8(float v[8], int r)
{
    const unsigned FULL = 0xffffffffu;
    const bool b4 = (r & 4) != 0, b2 = (r & 2) != 0, b1 = (r & 1) != 0;
    float s = reduce_scatter8(v, r);
    float gg = __shfl_xor_sync(FULL, s, 1, 8);
    float p0 = b1 ? gg : s;
    float p1 = b1 ? s : gg;
    float g0 = __shfl_xor_sync(FULL, p0, 2, 8);
    float g1 = __shfl_xor_sync(FULL, p1, 2, 8);
    float qd[4];
    qd[0] = b2 ? g0 : p0;  qd[1] = b2 ? g1 : p1;
    qd[2] = b2 ? p0 : g0;  qd[3] = b2 ? p1 : g1;
    #pragma unroll
    for (int i = 0; i < 4; i++) {
        float gi = __shfl_xor_sync(FULL, qd[i], 4, 8);
        v[i]     = b4 ? gi : qd[i];
        v[4 + i] = b4 ? qd[i] : gi;
    }
}

// routing + squash + store; priors packed: pri2[k][j] = (m=2j, m=2j+1)
template<int CNT>
__device__ __forceinline__ void route_and_store(
    ull pri2[CNT][4], int n, int p, int q,
    const float* __restrict__ bs, float* __restrict__ y)
{
    constexpr float NZEROS = (float)(72 - 8 * CNT);
    const unsigned FULL = 0xffffffffu;
    const int tid = threadIdx.x;
    const int r = tid & 7;

    // init: mean over all 72 (zeros included in divisor)
    float o[8];
    {
        ull s2[4];
        #pragma unroll
        for (int j = 0; j < 4; j++) s2[j] = pri2[0][j];
        #pragma unroll
        for (int k = 1; k < CNT; k++)
            #pragma unroll
            for (int j = 0; j < 4; j++) s2[j] = add2(s2[j], pri2[k][j]);
        #pragma unroll
        for (int j = 0; j < 4; j++) unpack2(s2[j], o[2 * j], o[2 * j + 1]);
    }
    allreduce8(o, r);
    #pragma unroll
    for (int m = 0; m < 8; m++) o[m] *= (1.0f / 72.0f);

    #pragma unroll
    for (int it = 0; it < 2; it++) {
        float sn = 0.f;
        #pragma unroll
        for (int m = 0; m < 8; m++) sn = fmaf(o[m], o[m], sn);
        float inv = rsqrtf(fmaxf(sn, 1e-24f));

        ull o2[4];
        #pragma unroll
        for (int j = 0; j < 4; j++) o2[j] = pack2(o[2 * j], o[2 * j + 1]);

        float e[CNT];
        float z = 0.f;
        #pragma unroll
        for (int k = 0; k < CNT; k++) {
            ull t = mul2(pri2[k][0], o2[0]);
            t = fma2(pri2[k][1], o2[1], t);
            t = fma2(pri2[k][2], o2[2], t);
            t = fma2(pri2[k][3], o2[3], t);
            float ta, tb; unpack2(t, ta, tb);
            e[k] = __expf((ta + tb) * inv);
            z += e[k];
        }
        z += __shfl_xor_sync(FULL, z, 1, 8);
        z += __shfl_xor_sync(FULL, z, 2, 8);
        z += __shfl_xor_sync(FULL, z, 4, 8);
        z += NZEROS;

        ull acc2[4];
        {
            ull e2 = pack2(e[0], e[0]);
            #pragma unroll
            for (int j = 0; j < 4; j++) acc2[j] = mul2(e2, pri2[0][j]);
        }
        #pragma unroll
        for (int k = 1; k < CNT; k++) {
            ull e2 = pack2(e[k], e[k]);
            #pragma unroll
            for (int j = 0; j < 4; j++) acc2[j] = fma2(e2, pri2[k][j], acc2[j]);
        }
        float acc[8];
        #pragma unroll
        for (int j = 0; j < 4; j++) unpack2(acc2[j], acc[2 * j], acc[2 * j + 1]);
        allreduce8(acc, r);

        float rz = __fdividef(1.0f, z);
        #pragma unroll
        for (int m = 0; m < 8; m++) o[m] = acc[m] * rz;
    }

    // final iteration: reduce-scatter only (lane r keeps component r)
    {
        float sn = 0.f;
        #pragma unroll
        for (int m = 0; m < 8; m++) sn = fmaf(o[m], o[m], sn);
        float inv = rsqrtf(fmaxf(sn, 1e-24f));

        ull o2[4];
        #pragma unroll
        for (int j = 0; j < 4; j++) o2[j] = pack2(o[2 * j], o[2 * j + 1]);

        float e[CNT];
        float z = 0.f;
        #pragma unroll
        for (int k = 0; k < CNT; k++) {
            ull t = mul2(pri2[k][0], o2[0]);
            t = fma2(pri2[k][1], o2[1], t);
            t = fma2(pri2[k][2], o2[2], t);
            t = fma2(pri2[k][3], o2[3], t);
            float ta, tb; unpack2(t, ta, tb);
            e[k] = __expf((ta + tb) * inv);
            z += e[k];
        }
        z += __shfl_xor_sync(FULL, z, 1, 8);
        z += __shfl_xor_sync(FULL, z, 2, 8);
        z += __shfl_xor_sync(FULL, z, 4, 8);
        z += NZEROS;

        ull acc2[4];
        {
            ull e2 = pack2(e[0], e[0]);
            #pragma unroll
            for (int j = 0; j < 4; j++) acc2[j] = mul2(e2, pri2[0][j]);
        }
        #pragma unroll
        for (int k = 1; k < CNT; k++) {
            ull e2 = pack2(e[k], e[k]);
            #pragma unroll
            for (int j = 0; j < 4; j++) acc2[j] = fma2(e2, pri2[k][j], acc2[j]);
        }
        float acc[8];
        #pragma unroll
        for (int j = 0; j < 4; j++) unpack2(acc2[j], acc[2 * j], acc[2 * j + 1]);

        float s   = reduce_scatter8(acc, r);
        float orr = s * __fdividef(1.0f, z);

        float sq = orr * orr;
        sq += __shfl_xor_sync(FULL, sq, 1, 8);
        sq += __shfl_xor_sync(FULL, sq, 2, 8);
        sq += __shfl_xor_sync(FULL, sq, 4, 8);

        float scale = sq / ((1.0f + sq) * sqrtf(sq + 1e-12f));
        y[((n * 64 + tid) * 64 + p) * 64 + q] = orr * scale + bs[tid];
    }
}

__device__ __forceinline__ void load8(float dst[8], const float* src, bool valid)
{
    if (valid) {
        float4 u0 = *(const float4*)(src);
        float4 u1 = *(const float4*)(src + 4);
        dst[0] = u0.x; dst[1] = u0.y; dst[2] = u0.z; dst[3] = u0.w;
        dst[4] = u1.x; dst[5] = u1.y; dst[6] = u1.z; dst[7] = u1.w;
    } else {
        #pragma unroll
        for (int i = 0; i < 8; i++) dst[i] = 0.f;
    }
}

// NTAP<=2 classes: x direct from g_xt (registers), packed-FMA priors.
template<int NTAP, int BASE>
__device__ __forceinline__ void caps_direct(
    int n, int p, int q, int i0, int j0, bool ivar,   // ivar: tap varies i (OE)
    const float* __restrict__ bs, float* __restrict__ y)
{
    const int tid = threadIdx.x;
    const int g = tid >> 3;
    const int r = tid & 7;
    const int tp = r & (NTAP - 1);
    const int f0 = r / NTAP;

    float xr[NTAP][8];   // [k][l], fields f0 + k*(8/NTAP)
    if (NTAP == 1) {
        const float* xb = g_xt + ((n * 32 + i0) * 32 + j0) * 64 + f0 * 8;
        load8(xr[0], xb, true);
    } else {
        int i = ivar ? (i0 + tp) : i0;
        int j = ivar ? j0 : (j0 + tp);
        bool valid = (i < 32) && (j < 32);     // tap 2 at p/q == 63
        const float* xb = g_xt + ((n * 32 + i) * 32 + j) * 64;
        load8(xr[0], xb + f0 * 8, valid);
        load8(xr[1], xb + (f0 + 4) * 8, valid);
    }

    const float* wrow = g_wpk + BASE + (g * NTAP + tp) * 8;

    ull pri2[NTAP][4];
    #pragma unroll
    for (int k = 0; k < NTAP; k++)
        #pragma unroll
        for (int j = 0; j < 4; j++) pri2[k][j] = 0ull;

    #pragma unroll
    for (int l = 0; l < 8; l++) {
        const ulonglong2* wp = (const ulonglong2*)(wrow + l * (64 * NTAP));
        ulonglong2 wa = wp[0];            // (m0,m1),(m2,m3)
        ulonglong2 wb = wp[1];            // (m4,m5),(m6,m7)
        #pragma unroll
        for (int k = 0; k < NTAP; k++) {
            ull xx = pack2(xr[k][l], xr[k][l]);
            pri2[k][0] = fma2(xx, wa.x, pri2[k][0]);
            pri2[k][1] = fma2(xx, wa.y, pri2[k][1]);
            pri2[k][2] = fma2(xx, wb.x, pri2[k][2]);
            pri2[k][3] = fma2(xx, wb.y, pri2[k][3]);
        }
    }

    route_and_store<NTAP>(pri2, n, p, q, bs, y);
}

// OO class: x staged in smem pitch-9 (conflict-free), packed-FMA priors.
__device__ __forceinline__ void caps_oo(
    int n, int p, int q, float* __restrict__ s_x,
    const float* __restrict__ bs, float* __restrict__ y)
{
    const int tid = threadIdx.x;
    const int g = tid >> 3;
    const int r = tid & 7;

    const int i0 = p >> 1, j0 = q >> 1;   // p,q odd: (p-1)/2
    // stage: s_x[pos*72 + f*9 + l], pos = a*2+b
    #pragma unroll
    for (int pos = 0; pos < 4; pos++) {
        int i = i0 + (pos >> 1);
        int j = j0 + (pos & 1);
        bool valid = (i < 32) && (j < 32);
        float v = valid ? g_xt[((n * 32 + i) * 32 + j) * 64 + tid] : 0.f;
        s_x[pos * 72 + (tid >> 3) * 9 + (tid & 7)] = v;
    }
    __syncthreads();

    const int tp = r & 3;
    const int f0 = r >> 2;
    const float* wrow = g_wpk + 2560 + (g * 4 + tp) * 8;
    const float* xrow = s_x + tp * 72 + f0 * 9;   // field f0+2k -> + k*18

    ull pri2[4][4];
    #pragma unroll
    for (int k = 0; k < 4; k++)
        #pragma unroll
        for (int j = 0; j < 4; j++) pri2[k][j] = 0ull;

    #pragma unroll
    for (int l = 0; l < 8; l++) {
        const ulonglong2* wp = (const ulonglong2*)(wrow + l * 256);
        ulonglong2 wa = wp[0];
        ulonglong2 wb = wp[1];
        #pragma unroll
        for (int k = 0; k < 4; k++) {
            float xv = xrow[k * 18 + l];
            ull xx = pack2(xv, xv);
            pri2[k][0] = fma2(xx, wa.x, pri2[k][0]);
            pri2[k][1] = fma2(xx, wa.y, pri2[k][1]);
            pri2[k][2] = fma2(xx, wb.x, pri2[k][2]);
            pri2[k][3] = fma2(xx, wb.y, pri2[k][3]);
        }
    }

    route_and_store<4>(pri2, n, p, q, bs, y);
}

__global__ __launch_bounds__(64, 16)
void caps_kernel(const float* __restrict__ bs, float* __restrict__ y)
{
    __shared__ float s_x[4 * 72];

    const int pix = blockIdx.x;
    const int q = pix & 63;
    const int p = (pix >> 6) & 63;
    const int n = pix >> 12;

    const bool po = (p & 1) != 0;
    const bool qo = (q & 1) != 0;

    if (!po && !qo)
        caps_direct<1, 0>(n, p, q, p >> 1, q >> 1, false, bs, y);
    else if (!po)
        caps_direct<2, 512>(n, p, q, p >> 1, q >> 1, false, bs, y);   // j = j0+tp
    else if (!qo)
        caps_direct<2, 1536>(n, p, q, p >> 1, q >> 1, true, bs, y);   // i = i0+tp
    else
        caps_oo(n, p, q, s_x, bs, y);
}

extern "C" void kernel_launch(void* const* d_in, const int* in_sizes, int n_in,
                              void* d_out, int out_size) {
    const float* x  = (const float*)d_in[0];
    const float* wt = (const float*)d_in[1];
    const float* bs = (const float*)d_in[2];
    float* y = (float*)d_out;
    prep_kernel<<<129, 256>>>(x, wt);
    caps_kernel<<<2 * 64 * 64, 64>>>(bs, y);
}